// round 8
// baseline (speedup 1.0000x reference)
#include <cuda_runtime.h>

// ---------------------------------------------------------------------------
// SSIM (16,3,512,512) fp32, 11x11 gaussian (sigma=1.5), zero padding.
// Round-8 (base R7, 84.3us): occupancy push 7 -> 8 blocks/SM.
//  * __launch_bounds__(128, 8): ptxas reg target 64 (was 72 -> 7 blocks).
//  * reg trims: loader uses one base pointer + 32-bit offsets; W2 scalars.
//  * smem 26.0KB -> 25.4KB (RW 144) so 8 blocks fit in 228KB.
// Model: fma pipe 64.4% busy but issue-starved (28 warps/SM); +4 warps
// should lift fma to ~75% -> ~72us.
// ---------------------------------------------------------------------------

#define IMG_H 512
#define IMG_W 512
#define N_PLANES 48
#define N_BLOCKS (48 * 4 * 16)
#define TOTAL_PIX 12582912.0

#define GW0 0.26601172f
#define GW1 0.21300554f
#define GW2 0.10936069f
#define GW3 0.03600077f
#define GW4 0.00759876f
#define GW5 0.00102842f

__device__ double g_acc;
__device__ unsigned int g_count;

typedef unsigned long long u64;

__device__ __forceinline__ u64 pk2(float lo, float hi) {
    u64 r; asm("mov.b64 %0, {%1, %2};" : "=l"(r) : "f"(lo), "f"(hi)); return r;
}
__device__ __forceinline__ float2 upk2(u64 v) {
    float2 r; asm("mov.b64 {%0, %1}, %2;" : "=f"(r.x), "=f"(r.y) : "l"(v)); return r;
}
__device__ __forceinline__ u64 fma2(u64 a, u64 b, u64 c) {
    u64 d; asm("fma.rn.f32x2 %0, %1, %2, %3;" : "=l"(d) : "l"(a), "l"(b), "l"(c)); return d;
}
__device__ __forceinline__ u64 mul2(u64 a, u64 b) {
    u64 d; asm("mul.rn.f32x2 %0, %1, %2;" : "=l"(d) : "l"(a), "l"(b)); return d;
}
__device__ __forceinline__ void cp16(unsigned dst, const float* src, unsigned rs) {
    asm volatile("cp.async.cg.shared.global [%0], [%1], 16, %2;"
                 :: "r"(dst), "l"(src), "r"(rs));
}

// smem row: 144 floats, covering global cols [col0-8, col0+136)
// thread tx's 11-tap window: gcol = col0+tx-5+i -> smem idx tx+3+i (max 140)
#define RW 144
#define NCP 36                           // 16B chunks per row per array
#define ROW_STRIDE_B (2 * RW * 4)        // 1152 bytes
#define BUF_STRIDE_B (11 * 2 * RW * 4)   // 12672 bytes

__global__ __launch_bounds__(128, 8)
void ssim_kernel(const float* __restrict__ img1, const float* __restrict__ img2,
                 float* __restrict__ out) {
    const int plane = blockIdx.x;     // 0..47
    const int strip = blockIdx.y;     // 0..3   (column strips of 128)
    const int band  = blockIdx.z;     // 0..15  (row bands of 32)
    const int tx    = threadIdx.x;

    const int col0 = strip * 128;
    const int row0 = band * 32;

    const float* __restrict__ p1 = img1 + (size_t)plane * (IMG_H * IMG_W);
    const float* __restrict__ p2 = img2 + (size_t)plane * (IMG_H * IMG_W);

    // [buf][row][array(a/b)][col]
    __shared__ __align__(16) float smem[2][11][2][RW];

    unsigned sbase;
    asm("{ .reg .u64 t; cvta.to.shared.u64 t, %1; cvt.u32.u64 %0, t; }"
        : "=r"(sbase) : "l"((const void*)smem));

    // ---- loader constants: thread tx<72 owns one 16B chunk column ----
    // (first/last chunks of each row are always fully in-bounds or fully OOB
    //  only via row check: col range col0-8..col0+136; cols -8..-1 (strip 0)
    //  and 512..535 (strip 3) are OOB -> those chunks zfill)
    const int  larr  = (tx >= NCP) ? 1 : 0;
    const int  lpos  = tx - NCP * larr;              // 0..35
    const int  lgcol = col0 - 8 + lpos * 4;
    const bool lcolok = (tx < 2 * NCP) && ((unsigned)lgcol < (unsigned)IMG_W);
    const float* __restrict__ lbase = larr ? p2 : p1;
    const unsigned ldst = sbase + (unsigned)((larr * RW + lpos * 4) * 4);

    const u64 W2_0 = pk2(GW0, GW0), W2_1 = pk2(GW1, GW1), W2_2 = pk2(GW2, GW2);
    const u64 W2_3 = pk2(GW3, GW3), W2_4 = pk2(GW4, GW4), W2_5 = pk2(GW5, GW5);
    const u64 WT[11] = {W2_5, W2_4, W2_3, W2_2, W2_1, W2_0,
                        W2_1, W2_2, W2_3, W2_4, W2_5};
    const float GWs[11] = {GW5, GW4, GW3, GW2, GW1, GW0, GW1, GW2, GW3, GW4, GW5};

    u64 ring01[11], ringq[11];
#pragma unroll
    for (int k = 0; k < 11; ++k) { ring01[k] = 0ull; ringq[k] = 0ull; }

    float acc = 0.f;
    const float C1  = 1e-4f;
    const float C2  = 9e-4f;
    const float C2E = 9e-4f + 1e-6f;

    // ---- async chunk loader: 11 rows (a and b) into buffer bb ----
    auto load_chunk = [&](int t, int bb) {
        if (tx < 2 * NCP) {
            const int base = row0 - 5 + t * 11;
            const unsigned dbase = ldst + (unsigned)(bb * BUF_STRIDE_B);
#pragma unroll
            for (int r = 0; r < 11; ++r) {
                const int y = base + r;
                const bool ok = lcolok && ((unsigned)y < (unsigned)IMG_H);
                const int goff = ok ? (y * IMG_W + lgcol) : 0;
                cp16(dbase + (unsigned)(r * ROW_STRIDE_B), lbase + goff,
                     ok ? 16u : 0u);
            }
        }
        asm volatile("cp.async.commit_group;");
    };

    load_chunk(0, 0);

    // input rows n = t*11 + k, 4 chunks (44 slots); outputs for n in [10, 42)
    for (int t = 0; t < 4; ++t) {
        const int cur = t & 1;
        if (t < 3) {
            load_chunk(t + 1, cur ^ 1);
            asm volatile("cp.async.wait_group 1;");
        } else {
            asm volatile("cp.async.wait_group 0;");
        }
        __syncthreads();   // chunk t visible to all

#pragma unroll
        for (int k = 0; k < 11; ++k) {
            const float* sa = smem[cur][k][0];
            const float* sb = smem[cur][k][1];
            u64 h01 = 0ull, h23 = 0ull;
            float h4 = 0.f;
#pragma unroll
            for (int i = 0; i < 11; ++i) {
                const float a = sa[tx + 3 + i];
                const float b = sb[tx + 3 + i];
                const u64 vv = pk2(a, b);
                const u64 w  = WT[i];
                h01 = fma2(w, vv, h01);               // (+wa, +wb)
                const u64 p = mul2(w, vv);            // (wa, wb)
                h23 = fma2(p, vv, h23);               // (+wa^2, +wb^2)
                const float2 pf = upk2(p);
                h4 = fmaf(pf.x, b, h4);               // +w*a*b
            }
            const float2 hq = upk2(h23);
            ring01[k] = h01;
            ringq [k] = pk2(hq.x + hq.y, h4);

            const int n = t * 11 + k;
            if (n >= 10 && n < 42) {
                u64 m12 = 0ull, qv = 0ull;
#pragma unroll
                for (int j = 0; j < 11; ++j) {
                    const int s = (k + 1 + j) % 11;   // static after unroll
                    const u64 w = WT[j];
                    m12 = fma2(w, ring01[s], m12);
                    qv  = fma2(w, ringq [s], qv);
                }
                const float2 m = upk2(m12);           // (mu1, mu2)
                const float2 q = upk2(qv);            // (spp, s12)
                const float mu12  = m.x * m.y;
                const float musq  = fmaf(m.y, m.y, m.x * m.x);
                const float sig12 = q.y - mu12;
                const float sigpp = q.x - musq;
                const float v1  = fmaf(2.f, sig12, C2);
                const float v2  = sigpp + C2E;
                const float num = fmaf(2.f, mu12, C1) * v1;
                const float den = (musq + C1) * v2;
                acc += __fdividef(num, den);
            }
        }
        __syncthreads();   // buffer cur free for chunk t+2's loads
    }
    (void)GWs;

#pragma unroll
    for (int o = 16; o > 0; o >>= 1)
        acc += __shfl_xor_sync(0xFFFFFFFFu, acc, o);

    __shared__ float wsum[4];
    if ((tx & 31) == 0) wsum[tx >> 5] = acc;
    __syncthreads();

    if (tx == 0) {
        const float s = wsum[0] + wsum[1] + wsum[2] + wsum[3];
        atomicAdd(&g_acc, (double)s);
        __threadfence();
        const unsigned int done = atomicAdd(&g_count, 1u);
        if (done == (unsigned)(N_BLOCKS - 1)) {
            const double total = atomicAdd(&g_acc, 0.0);
            out[0] = (float)(total / TOTAL_PIX);
            g_acc = 0.0;
            g_count = 0u;
            __threadfence();
        }
    }
}

extern "C" void kernel_launch(void* const* d_in, const int* in_sizes, int n_in,
                              void* d_out, int out_size) {
    const float* img1 = (const float*)d_in[0];
    const float* img2 = (const float*)d_in[1];
    float* out = (float*)d_out;
    (void)in_sizes; (void)n_in; (void)out_size;

    dim3 grid(N_PLANES, 4, 16);
    ssim_kernel<<<grid, 128>>>(img1, img2, out);
}

// round 9
// speedup vs baseline: 1.1242x; 1.1242x over previous
#include <cuda_runtime.h>

// ---------------------------------------------------------------------------
// SSIM (16,3,512,512) fp32, 11x11 gaussian (sigma=1.5), zero padding.
// Round-9 (base R7 84.3us; R8 reg-squeeze regressed via spills -> reverted
// to 7 blocks/SM):
//  * sum/difference transform: c=a+b, d=a-b computed once per element
//    (in-place smem pre-pass, packed fma2 with +-1). All four window
//    moments derive from (Sum wc, Sum wd, Sum wc^2, Sum wd^2):
//      mu1^2+mu2^2=(C^2+D^2)/2, mu1*mu2=(C^2-D^2)/4,
//      spp=(Qc+Qd)/2, s12=(Qc-Qd)/4.
//    Horizontal tap: 3 packed ops, no scalar h4 -> 44->33 fma instrs/row.
//  * epilogue reworked with 0.5-scaled constants (same op count as R7).
// ---------------------------------------------------------------------------

#define IMG_H 512
#define IMG_W 512
#define N_PLANES 48
#define N_BLOCKS (48 * 4 * 16)
#define TOTAL_PIX 12582912.0

#define GW0 0.26601172f
#define GW1 0.21300554f
#define GW2 0.10936069f
#define GW3 0.03600077f
#define GW4 0.00759876f
#define GW5 0.00102842f

__device__ double g_acc;
__device__ unsigned int g_count;

typedef unsigned long long u64;

__device__ __forceinline__ u64 pk2(float lo, float hi) {
    u64 r; asm("mov.b64 %0, {%1, %2};" : "=l"(r) : "f"(lo), "f"(hi)); return r;
}
__device__ __forceinline__ float2 upk2(u64 v) {
    float2 r; asm("mov.b64 {%0, %1}, %2;" : "=f"(r.x), "=f"(r.y) : "l"(v)); return r;
}
__device__ __forceinline__ u64 fma2(u64 a, u64 b, u64 c) {
    u64 d; asm("fma.rn.f32x2 %0, %1, %2, %3;" : "=l"(d) : "l"(a), "l"(b), "l"(c)); return d;
}
__device__ __forceinline__ u64 mul2(u64 a, u64 b) {
    u64 d; asm("mul.rn.f32x2 %0, %1, %2;" : "=l"(d) : "l"(a), "l"(b)); return d;
}
__device__ __forceinline__ void cp16(unsigned dst, const float* src, unsigned rs) {
    asm volatile("cp.async.cg.shared.global [%0], [%1], 16, %2;"
                 :: "r"(dst), "l"(src), "r"(rs));
}

// smem row: 144 floats per plane, global cols [col0-8, col0+136)
// thread tx's 11-tap window: smem idx tx+3 .. tx+13 (max 140 < 144)
#define RW 144
#define NCP 36                           // 16B chunks per row per plane
#define ROW_STRIDE_B (2 * RW * 4)        // 1152 bytes (plane a + plane b)
#define BUF_STRIDE_B (11 * 2 * RW * 4)   // 12672 bytes
#define NPAIR (RW / 2)                   // 72 u64 pairs per plane row
#define PRE_TASKS (11 * NPAIR)           // 792

__global__ __launch_bounds__(128, 7)
void ssim_kernel(const float* __restrict__ img1, const float* __restrict__ img2,
                 float* __restrict__ out) {
    const int plane = blockIdx.x;     // 0..47
    const int strip = blockIdx.y;     // 0..3
    const int band  = blockIdx.z;     // 0..15  (row bands of 32)
    const int tx    = threadIdx.x;

    const int col0 = strip * 128;
    const int row0 = band * 32;

    const float* __restrict__ p1 = img1 + (size_t)plane * (IMG_H * IMG_W);
    const float* __restrict__ p2 = img2 + (size_t)plane * (IMG_H * IMG_W);

    // [buf][row][plane(a/b -> c/d)][col]
    __shared__ __align__(16) float smem[2][11][2][RW];

    unsigned sbase;
    asm("{ .reg .u64 t; cvta.to.shared.u64 t, %1; cvt.u32.u64 %0, t; }"
        : "=r"(sbase) : "l"((const void*)smem));

    // loader: thread tx<72 owns one 16B chunk column (plane, pos)
    const int  larr  = (tx >= NCP) ? 1 : 0;
    const int  lpos  = tx - NCP * larr;
    const int  lgcol = col0 - 8 + lpos * 4;
    const bool lcolok = (tx < 2 * NCP) && ((unsigned)lgcol < (unsigned)IMG_W);
    const float* __restrict__ lbase = larr ? p2 : p1;
    const unsigned ldst = sbase + (unsigned)((larr * RW + lpos * 4) * 4);

    const u64 W2_0 = pk2(GW0, GW0), W2_1 = pk2(GW1, GW1), W2_2 = pk2(GW2, GW2);
    const u64 W2_3 = pk2(GW3, GW3), W2_4 = pk2(GW4, GW4), W2_5 = pk2(GW5, GW5);
    const u64 WT[11] = {W2_5, W2_4, W2_3, W2_2, W2_1, W2_0,
                        W2_1, W2_2, W2_3, W2_4, W2_5};
    const u64 POS1 = pk2(1.f, 1.f);
    const u64 NEG1 = pk2(-1.f, -1.f);

    u64 ring01[11], ringq[11];
#pragma unroll
    for (int k = 0; k < 11; ++k) { ring01[k] = 0ull; ringq[k] = 0ull; }

    float acc = 0.f;
    const float C1  = 1e-4f;
    const float C2  = 9e-4f;
    const float C2E = 9e-4f + 1e-6f;

    auto load_chunk = [&](int t, int bb) {
        if (tx < 2 * NCP) {
            const int base = row0 - 5 + t * 11;
            const unsigned dbase = ldst + (unsigned)(bb * BUF_STRIDE_B);
#pragma unroll
            for (int r = 0; r < 11; ++r) {
                const int y = base + r;
                const bool ok = lcolok && ((unsigned)y < (unsigned)IMG_H);
                const int goff = ok ? (y * IMG_W + lgcol) : 0;
                cp16(dbase + (unsigned)(r * ROW_STRIDE_B), lbase + goff,
                     ok ? 16u : 0u);
            }
        }
        asm volatile("cp.async.commit_group;");
    };

    load_chunk(0, 0);

    // input rows n = t*11 + k, 4 chunks; outputs for n in [10, 42)
    for (int t = 0; t < 4; ++t) {
        const int cur = t & 1;
        if (t < 3) {
            load_chunk(t + 1, cur ^ 1);
            asm volatile("cp.async.wait_group 1;");
        } else {
            asm volatile("cp.async.wait_group 0;");
        }
        __syncthreads();   // chunk t data visible

        // pre-pass: (a,b) -> (c,d) = (a+b, a-b), in place, packed pairs.
        // each thread RMWs only its own u64 slots -> no cross-thread hazard.
        {
            u64* U = (u64*)smem[cur];   // [11 rows][144 u64]; a-plane 0..71, b-plane 72..143
#pragma unroll 1
            for (int j = tx; j < PRE_TASKS; j += 128) {
                const int r  = j / NPAIR;
                const int pr = j - r * NPAIR;
                u64* pa = U + (r * (2 * NPAIR) + pr);
                u64* pb = pa + NPAIR;
                const u64 aa = *pa;
                const u64 bb = *pb;
                *pa = fma2(bb, POS1, aa);   // c pair
                *pb = fma2(bb, NEG1, aa);   // d pair
            }
        }
        __syncthreads();   // c/d visible to all

#pragma unroll
        for (int k = 0; k < 11; ++k) {
            const float* sc = smem[cur][k][0];
            const float* sd = smem[cur][k][1];
            u64 h01 = 0ull, hq = 0ull;
#pragma unroll
            for (int i = 0; i < 11; ++i) {
                const u64 vv = pk2(sc[tx + 3 + i], sd[tx + 3 + i]);  // (c,d)
                const u64 w  = WT[i];
                h01 = fma2(w, vv, h01);            // (+wc, +wd)
                const u64 p = mul2(w, vv);         // (wc, wd)
                hq  = fma2(p, vv, hq);             // (+wc^2, +wd^2)
            }
            ring01[k] = h01;
            ringq [k] = hq;

            const int n = t * 11 + k;
            if (n >= 10 && n < 42) {
                u64 m12 = 0ull, qv = 0ull;
#pragma unroll
                for (int j = 0; j < 11; ++j) {
                    const int s = (k + 1 + j) % 11;   // static after unroll
                    const u64 w = WT[j];
                    m12 = fma2(w, ring01[s], m12);    // (C, D)
                    qv  = fma2(w, ringq [s], qv);     // (Qc, Qd)
                }
                const u64 cd2 = mul2(m12, m12);           // (C^2, D^2)
                const u64 ev  = fma2(cd2, NEG1, qv);      // (Ec, Ed) = var terms
                const float2 s2 = upk2(cd2);
                const float2 e2 = upk2(ev);
                const float M = s2.x - s2.y;   // 4*mu1*mu2
                const float P = s2.x + s2.y;   // 2*(mu1^2+mu2^2)
                const float S = e2.x - e2.y;   // 4*sig12
                const float T = e2.x + e2.y;   // 2*sigpp
                const float num = fmaf(0.5f, M, C1) * fmaf(0.5f, S, C2);
                const float den = fmaf(0.5f, P, C1) * fmaf(0.5f, T, C2E);
                acc += __fdividef(num, den);
            }
        }
        __syncthreads();   // buffer cur free for chunk t+2's cp.async
    }

#pragma unroll
    for (int o = 16; o > 0; o >>= 1)
        acc += __shfl_xor_sync(0xFFFFFFFFu, acc, o);

    __shared__ float wsum[4];
    if ((tx & 31) == 0) wsum[tx >> 5] = acc;
    __syncthreads();

    if (tx == 0) {
        const float s = wsum[0] + wsum[1] + wsum[2] + wsum[3];
        atomicAdd(&g_acc, (double)s);
        __threadfence();
        const unsigned int done = atomicAdd(&g_count, 1u);
        if (done == (unsigned)(N_BLOCKS - 1)) {
            const double total = atomicAdd(&g_acc, 0.0);
            out[0] = (float)(total / TOTAL_PIX);
            g_acc = 0.0;
            g_count = 0u;
            __threadfence();
        }
    }
}

extern "C" void kernel_launch(void* const* d_in, const int* in_sizes, int n_in,
                              void* d_out, int out_size) {
    const float* img1 = (const float*)d_in[0];
    const float* img2 = (const float*)d_in[1];
    float* out = (float*)d_out;
    (void)in_sizes; (void)n_in; (void)out_size;

    dim3 grid(N_PLANES, 4, 16);
    ssim_kernel<<<grid, 128>>>(img1, img2, out);
}